// round 4
// baseline (speedup 1.0000x reference)
#include <cuda_runtime.h>
#include <math.h>

#define BB   4
#define CC   256
#define CSd  128
#define NN   4096
#define EPSc 1e-5f

typedef unsigned long long ull;

// ---------------- f32x2 packed-math helpers (sm_103a FFMA2) ----------------
__device__ __forceinline__ ull pack2(float x, float y){
    ull r; asm("mov.b64 %0, {%1,%2};" : "=l"(r) : "f"(x), "f"(y)); return r;
}
__device__ __forceinline__ void unpack2(ull v, float& x, float& y){
    asm("mov.b64 {%0,%1}, %2;" : "=f"(x), "=f"(y) : "l"(v));
}
__device__ __forceinline__ ull ffma2(ull a, ull b, ull c){
    ull d; asm("fma.rn.f32x2 %0, %1, %2, %3;" : "=l"(d) : "l"(a), "l"(b), "l"(c)); return d;
}
__device__ __forceinline__ ull fmul2(ull a, ull b){
    ull d; asm("mul.rn.f32x2 %0, %1, %2;" : "=l"(d) : "l"(a), "l"(b)); return d;
}

// ---------------- scratch (device globals; no allocations) ----------------
__device__ float d_Q[BB*CSd*NN];   // [b][cs][n] dim-major
__device__ float d_K[BB*CSd*NN];   // [b][cs][n] dim-major
__device__ float d_V[BB*NN*CSd];   // [b][n][cs] token-major
__device__ float d_O[BB*NN*CSd];   // [b][n][cs] token-major
__device__ float d_Y[BB*CC*NN];    // [b][c][n]
__device__ float d_scale[CC];
__device__ float d_shift[CC];

// ======================= Kernel A: QKV projections =========================
// grid (N/128, B, 3), block 256. Out tile 128(cs) x 128(n), 8x8 microtile, FFMA2.
__global__ __launch_bounds__(256) void qkv_kernel(
    const float* __restrict__ x,
    const float* __restrict__ Wq, const float* __restrict__ bq,
    const float* __restrict__ Wk, const float* __restrict__ bk,
    const float* __restrict__ Wv, const float* __restrict__ bv)
{
    __shared__ float Ws[128*37];   // Ws[cs][kc], stride 37 (conflict-free bcast)
    __shared__ float Xs[32*132];   // Xs[kc][n]
    const int z  = blockIdx.z;     // 0=Q 1=K 2=V
    const int b  = blockIdx.y;
    const int n0 = blockIdx.x * 128;
    const float* W    = (z==0) ? Wq : (z==1) ? Wk : Wv;
    const float* bias = (z==0) ? bq : (z==1) ? bk : bv;
    const int tid = threadIdx.x;
    const int ty = tid >> 4, tx = tid & 15;

    ull acc2[8][4];
    #pragma unroll
    for (int i = 0; i < 8; i++)
        #pragma unroll
        for (int j = 0; j < 4; j++) acc2[i][j] = 0ull;

    for (int k0 = 0; k0 < CC; k0 += 32) {
        #pragma unroll
        for (int it = 0; it < 16; it++) {
            int f = tid + it*256;
            int kc = f & 31, cs = f >> 5;
            Ws[cs*37 + kc] = W[cs*CC + k0 + kc];
        }
        #pragma unroll
        for (int it = 0; it < 16; it++) {
            int f = tid + it*256;
            int nn2 = f & 127, kc = f >> 7;
            Xs[kc*132 + nn2] = x[(b*CC + k0 + kc)*NN + n0 + nn2];
        }
        __syncthreads();
        #pragma unroll 4
        for (int kc = 0; kc < 32; kc++) {
            ull ad[8];
            #pragma unroll
            for (int i = 0; i < 8; i++) {
                float a = Ws[(ty*8+i)*37 + kc];
                ad[i] = pack2(a, a);
            }
            ulonglong2 x0 = *(const ulonglong2*)&Xs[kc*132 + tx*8];
            ulonglong2 x1 = *(const ulonglong2*)&Xs[kc*132 + tx*8 + 4];
            ull bb[4] = {x0.x, x0.y, x1.x, x1.y};
            #pragma unroll
            for (int i = 0; i < 8; i++)
                #pragma unroll
                for (int j = 0; j < 4; j++)
                    acc2[i][j] = ffma2(ad[i], bb[j], acc2[i][j]);
        }
        __syncthreads();
    }

    float accf[8][8];
    #pragma unroll
    for (int i = 0; i < 8; i++)
        #pragma unroll
        for (int j = 0; j < 4; j++)
            unpack2(acc2[i][j], accf[i][2*j], accf[i][2*j+1]);

    float bl[8];
    #pragma unroll
    for (int i = 0; i < 8; i++) bl[i] = bias[ty*8 + i];

    if (z < 2) {
        float* out = (z==0) ? d_Q : d_K;
        #pragma unroll
        for (int i = 0; i < 8; i++) {
            int cs = ty*8 + i;
            float* p = &out[(b*CSd + cs)*NN + n0 + tx*8];
            *(float4*)p       = make_float4(accf[i][0]+bl[i], accf[i][1]+bl[i], accf[i][2]+bl[i], accf[i][3]+bl[i]);
            *((float4*)p + 1) = make_float4(accf[i][4]+bl[i], accf[i][5]+bl[i], accf[i][6]+bl[i], accf[i][7]+bl[i]);
        }
    } else {
        #pragma unroll
        for (int j = 0; j < 8; j++) {
            int n = n0 + tx*8 + j;
            float* p = &d_V[(b*NN + n)*CSd + ty*8];
            *(float4*)p       = make_float4(accf[0][j]+bl[0], accf[1][j]+bl[1], accf[2][j]+bl[2], accf[3][j]+bl[3]);
            *((float4*)p + 1) = make_float4(accf[4][j]+bl[4], accf[5][j]+bl[5], accf[6][j]+bl[6], accf[7][j]+bl[7]);
        }
    }
}

// ======================= Kernel B: flash attention (fp32, FFMA2) ===========
// grid (N/128, B) = 128 CTAs, block 256, ~200KB dynamic smem, 1 CTA/SM.
// BM=128 q, BN=128 keys, d=128. 8x8 microtiles both phases.
// St row address: r*132 + ((r>>3)&1)*4  (ty-parity offset kills PV bcast conflict)
#define ST_ROW(r) ((r)*132 + (((r)>>3)&1)*4)
#define ATTN_SMEM_FLOATS (128*128 + 128*128 + (128*132 + 8) + 3*128)
#define ATTN_SMEM_BYTES  (ATTN_SMEM_FLOATS*4)

__global__ __launch_bounds__(256, 1) void attn_kernel()
{
    extern __shared__ float sm[];
    float* Qt    = sm;                  // [128 d][128 q] stride 128
    float* Bf    = Qt + 128*128;        // K: [128 d][128 k] then V: [128 k][128 d]
    float* St    = Bf + 128*128;        // [128 q][132+off]
    float* mrow  = St + 128*132 + 8;    // [128]
    float* lrow  = mrow + 128;          // [128]
    float* rsrow = lrow + 128;          // [128]

    const int b  = blockIdx.y;
    const int q0 = blockIdx.x * 128;
    const int tid = threadIdx.x;
    const int ty = tid >> 4, tx = tid & 15;

    // load Q tile dim-major (coalesced float4)
    #pragma unroll
    for (int it = 0; it < 16; it++) {
        int g = tid + it*256;               // float4 index over 4096
        int q4 = g & 31, cs = g >> 5;
        *(float4*)&Qt[cs*128 + q4*4] =
            *(const float4*)&d_Q[(b*CSd + cs)*NN + q0 + q4*4];
    }
    if (tid < 128) { mrow[tid] = -1e30f; lrow[tid] = 0.f; }

    int strow[8];
    #pragma unroll
    for (int i = 0; i < 8; i++) strow[i] = (ty*8+i)*132 + (ty&1)*4;

    ull o2[8][4];
    #pragma unroll
    for (int i = 0; i < 8; i++)
        #pragma unroll
        for (int j = 0; j < 4; j++) o2[i][j] = 0ull;

    for (int kt = 0; kt < NN/128; kt++) {
        const int kb = kt * 128;
        __syncthreads();                      // Bf free (prev PV done); Qt ready
        // ---- load K tile: Bf[dim][key] ----
        #pragma unroll
        for (int it = 0; it < 16; it++) {
            int g = tid + it*256;
            int k4 = g & 31, cs = g >> 5;
            *(float4*)&Bf[cs*128 + k4*4] =
                *(const float4*)&d_K[(b*CSd + cs)*NN + kb + k4*4];
        }
        __syncthreads();

        // ---- S = Q^T.K : 8x8 microtile, FFMA2 ----
        ull s2[8][4];
        #pragma unroll
        for (int i = 0; i < 8; i++)
            #pragma unroll
            for (int j = 0; j < 4; j++) s2[i][j] = 0ull;
        #pragma unroll 2
        for (int k = 0; k < 128; k++) {
            float4 qa0 = *(const float4*)&Qt[k*128 + ty*8];
            float4 qa1 = *(const float4*)&Qt[k*128 + ty*8 + 4];
            ull ad[8];
            ad[0]=pack2(qa0.x,qa0.x); ad[1]=pack2(qa0.y,qa0.y);
            ad[2]=pack2(qa0.z,qa0.z); ad[3]=pack2(qa0.w,qa0.w);
            ad[4]=pack2(qa1.x,qa1.x); ad[5]=pack2(qa1.y,qa1.y);
            ad[6]=pack2(qa1.z,qa1.z); ad[7]=pack2(qa1.w,qa1.w);
            ulonglong2 k0v = *(const ulonglong2*)&Bf[k*128 + tx*8];
            ulonglong2 k1v = *(const ulonglong2*)&Bf[k*128 + tx*8 + 4];
            ull bb[4] = {k0v.x, k0v.y, k1v.x, k1v.y};
            #pragma unroll
            for (int i = 0; i < 8; i++)
                #pragma unroll
                for (int j = 0; j < 4; j++)
                    s2[i][j] = ffma2(ad[i], bb[j], s2[i][j]);
        }
        // store logits: St[q][key]
        #pragma unroll
        for (int i = 0; i < 8; i++) {
            *(ulonglong2*)&St[strow[i] + tx*8]     = make_ulonglong2(s2[i][0], s2[i][1]);
            *(ulonglong2*)&St[strow[i] + tx*8 + 4] = make_ulonglong2(s2[i][2], s2[i][3]);
        }
        __syncthreads();                     // St visible; K reads done

        // ---- load V tile into Bf (K is dead) ----
        #pragma unroll
        for (int it = 0; it < 16; it++) {
            int g = tid + it*256;
            int c4 = g & 31, kk = g >> 5;
            *(float4*)&Bf[kk*128 + c4*4] =
                *(const float4*)&d_V[(b*NN + kb + kk)*CSd + c4*4];
        }

        // ---- online softmax: 2 threads/row, rotated sweeps ----
        {
            const int r = tid >> 1, sub = tid & 1;
            const int ro = ST_ROW(r);
            float tm = -1e30f;
            #pragma unroll 8
            for (int t = 0; t < 64; t++) {
                int c = sub*64 + ((t + r) & 63);
                tm = fmaxf(tm, St[ro + c]);
            }
            tm = fmaxf(tm, __shfl_xor_sync(0xffffffffu, tm, 1));
            float mo = mrow[r];
            float nm = fmaxf(mo, tm);
            float sum = 0.f;
            #pragma unroll 8
            for (int t = 0; t < 64; t++) {
                int c = sub*64 + ((t + r) & 63);
                float p = __expf(St[ro + c] - nm);
                St[ro + c] = p;
                sum += p;
            }
            sum += __shfl_xor_sync(0xffffffffu, sum, 1);
            if (sub == 0) {
                float scv = __expf(mo - nm);
                lrow[r] = lrow[r]*scv + sum;
                mrow[r] = nm;
                rsrow[r] = scv;
            }
        }
        __syncthreads();                     // P + V + rsrow ready

        // ---- rescale, then O += P.V : 8x8 microtile, FFMA2 ----
        #pragma unroll
        for (int i = 0; i < 8; i++) {
            float scl = rsrow[ty*8 + i];
            ull sd = pack2(scl, scl);
            #pragma unroll
            for (int j = 0; j < 4; j++) o2[i][j] = fmul2(o2[i][j], sd);
        }
        #pragma unroll 2
        for (int k = 0; k < 128; k++) {
            ull pd[8];
            #pragma unroll
            for (int i = 0; i < 8; i++) {
                float p = St[strow[i] + k];
                pd[i] = pack2(p, p);
            }
            ulonglong2 v0 = *(const ulonglong2*)&Bf[k*128 + tx*8];
            ulonglong2 v1 = *(const ulonglong2*)&Bf[k*128 + tx*8 + 4];
            ull vv[4] = {v0.x, v0.y, v1.x, v1.y};
            #pragma unroll
            for (int i = 0; i < 8; i++)
                #pragma unroll
                for (int j = 0; j < 4; j++)
                    o2[i][j] = ffma2(pd[i], vv[j], o2[i][j]);
        }
    }

    #pragma unroll
    for (int i = 0; i < 8; i++) {
        float inv = 1.0f / lrow[ty*8 + i];
        float of[8];
        #pragma unroll
        for (int j = 0; j < 4; j++) unpack2(o2[i][j], of[2*j], of[2*j+1]);
        int n = q0 + ty*8 + i;
        float* p = &d_O[(b*NN + n)*CSd + tx*8];
        *(float4*)p       = make_float4(of[0]*inv, of[1]*inv, of[2]*inv, of[3]*inv);
        *((float4*)p + 1) = make_float4(of[4]*inv, of[5]*inv, of[6]*inv, of[7]*inv);
    }
}

// ======================= Kernel C: output projection (FFMA2) ===============
// grid (N/128, C/128, B), block 256.
__global__ __launch_bounds__(256) void oproj_kernel(
    const float* __restrict__ Wo, const float* __restrict__ bo)
{
    __shared__ float Wos[128*37];  // Wos[c][kc]
    __shared__ float Os[32*132];   // Os[kc][n]
    const int b  = blockIdx.z;
    const int c0 = blockIdx.y * 128;
    const int n0 = blockIdx.x * 128;
    const int tid = threadIdx.x;
    const int ty = tid >> 4, tx = tid & 15;

    ull acc2[8][4];
    #pragma unroll
    for (int i = 0; i < 8; i++)
        #pragma unroll
        for (int j = 0; j < 4; j++) acc2[i][j] = 0ull;

    for (int k0 = 0; k0 < CSd; k0 += 32) {
        #pragma unroll
        for (int it = 0; it < 16; it++) {
            int f = tid + it*256;
            int kc = f & 31, c = f >> 5;
            Wos[c*37 + kc] = Wo[(c0 + c)*CSd + k0 + kc];
        }
        #pragma unroll
        for (int it = 0; it < 16; it++) {
            int f = tid + it*256;
            int kc = f & 31, n2 = f >> 5;
            Os[kc*132 + n2] = d_O[(b*NN + n0 + n2)*CSd + k0 + kc];
        }
        __syncthreads();
        #pragma unroll 4
        for (int kc = 0; kc < 32; kc++) {
            ull ad[8];
            #pragma unroll
            for (int i = 0; i < 8; i++) {
                float a = Wos[(ty*8+i)*37 + kc];
                ad[i] = pack2(a, a);
            }
            ulonglong2 x0 = *(const ulonglong2*)&Os[kc*132 + tx*8];
            ulonglong2 x1 = *(const ulonglong2*)&Os[kc*132 + tx*8 + 4];
            ull bb[4] = {x0.x, x0.y, x1.x, x1.y};
            #pragma unroll
            for (int i = 0; i < 8; i++)
                #pragma unroll
                for (int j = 0; j < 4; j++)
                    acc2[i][j] = ffma2(ad[i], bb[j], acc2[i][j]);
        }
        __syncthreads();
    }

    #pragma unroll
    for (int i = 0; i < 8; i++) {
        float accf[8];
        #pragma unroll
        for (int j = 0; j < 4; j++) unpack2(acc2[i][j], accf[2*j], accf[2*j+1]);
        int c = c0 + ty*8 + i;
        float bv2 = bo[c];
        float* p = &d_Y[(b*CC + c)*NN + n0 + tx*8];
        *(float4*)p       = make_float4(accf[0]+bv2, accf[1]+bv2, accf[2]+bv2, accf[3]+bv2);
        *((float4*)p + 1) = make_float4(accf[4]+bv2, accf[5]+bv2, accf[6]+bv2, accf[7]+bv2);
    }
}

// ======================= Kernel D: BN stats (deterministic) =================
__global__ __launch_bounds__(256) void bnstat_kernel(
    const float* __restrict__ gamma, const float* __restrict__ beta)
{
    __shared__ float rs[256], rs2[256];
    const int c = blockIdx.x, tid = threadIdx.x;
    float s = 0.f, s2 = 0.f;
    #pragma unroll 4
    for (int j = 0; j < 64; j++) {
        int idx = tid + j*256;            // over B*N = 16384
        int bb2 = idx >> 12, nn2 = idx & 4095;
        float v = d_Y[(bb2*CC + c)*NN + nn2];
        s += v; s2 += v*v;
    }
    rs[tid] = s; rs2[tid] = s2;
    __syncthreads();
    for (int off = 128; off > 0; off >>= 1) {
        if (tid < off) { rs[tid] += rs[tid+off]; rs2[tid] += rs2[tid+off]; }
        __syncthreads();
    }
    if (tid == 0) {
        float mean = rs[0]  * (1.f/16384.f);
        float var  = rs2[0] * (1.f/16384.f) - mean*mean;
        float sc = gamma[c] * rsqrtf(var + EPSc);
        d_scale[c] = sc;
        d_shift[c] = beta[c] - mean*sc;
    }
}

// ======================= Kernel E: BN affine + ReLU + residual ==============
__global__ __launch_bounds__(256) void epilogue_kernel(
    const float* __restrict__ x, float* __restrict__ out)
{
    int i4 = blockIdx.x*256 + threadIdx.x;     // < 1048576 float4s
    int idx = i4 * 4;
    int c = (idx >> 12) & 255;
    float sc = d_scale[c], sh = d_shift[c];
    float4 y   = *(const float4*)&d_Y[idx];
    float4 xin = ((const float4*)x)[i4];
    float4 r;
    r.x = fmaxf(fmaf(y.x, sc, sh), 0.f) + xin.x;
    r.y = fmaxf(fmaf(y.y, sc, sh), 0.f) + xin.y;
    r.z = fmaxf(fmaf(y.z, sc, sh), 0.f) + xin.z;
    r.w = fmaxf(fmaf(y.w, sc, sh), 0.f) + xin.w;
    ((float4*)out)[i4] = r;
}

// ============================ launch =======================================
extern "C" void kernel_launch(void* const* d_in, const int* in_sizes, int n_in,
                              void* d_out, int out_size)
{
    const float* x     = (const float*)d_in[0];
    const float* Wq    = (const float*)d_in[1];
    const float* bq    = (const float*)d_in[2];
    const float* Wk    = (const float*)d_in[3];
    const float* bk    = (const float*)d_in[4];
    const float* Wv    = (const float*)d_in[5];
    const float* bv    = (const float*)d_in[6];
    const float* Wo    = (const float*)d_in[7];
    const float* bo    = (const float*)d_in[8];
    const float* gamma = (const float*)d_in[9];
    const float* beta  = (const float*)d_in[10];
    float* out = (float*)d_out;

    cudaFuncSetAttribute(attn_kernel,
                         cudaFuncAttributeMaxDynamicSharedMemorySize,
                         ATTN_SMEM_BYTES);

    qkv_kernel<<<dim3(NN/128, BB, 3), 256>>>(x, Wq, bq, Wk, bk, Wv, bv);
    attn_kernel<<<dim3(NN/128, BB), 256, ATTN_SMEM_BYTES>>>();
    oproj_kernel<<<dim3(NN/128, CC/128, BB), 256>>>(Wo, bo);
    bnstat_kernel<<<CC, 256>>>(gamma, beta);
    epilogue_kernel<<<(BB*CC*NN)/4/256, 256>>>(x, out);
}

// round 6
// speedup vs baseline: 2.3821x; 2.3821x over previous
#include <cuda_runtime.h>
#include <math.h>
#include <stdint.h>

#define BB   4
#define CC   256
#define CSd  128
#define NN   4096
#define EPSc 1e-5f

typedef unsigned long long ull;
typedef unsigned int u32;

// ---------------- FFMA2 helpers ----------------
__device__ __forceinline__ ull pack2(float x, float y){
    ull r; asm("mov.b64 %0, {%1,%2};" : "=l"(r) : "f"(x), "f"(y)); return r;
}
__device__ __forceinline__ void unpack2(ull v, float& x, float& y){
    asm("mov.b64 {%0,%1}, %2;" : "=f"(x), "=f"(y) : "l"(v));
}
__device__ __forceinline__ ull ffma2(ull a, ull b, ull c){
    ull d; asm("fma.rn.f32x2 %0, %1, %2, %3;" : "=l"(d) : "l"(a), "l"(b), "l"(c)); return d;
}
// bf16x2 pack: low half = bf16(v0), high half = bf16(v1)
__device__ __forceinline__ u32 cvt_bf2(float v1, float v0){
    u32 r; asm("cvt.rn.bf16x2.f32 %0, %1, %2;" : "=r"(r) : "f"(v1), "f"(v0)); return r;
}
__device__ __forceinline__ u32 smem_u32(const void* p){
    u32 a; asm("{ .reg .u64 t; cvta.to.shared.u64 t, %1; cvt.u32.u64 %0, t; }" : "=r"(a) : "l"(p));
    return a;
}

// ---------------- warp-MMA helpers (baseline PTX, sm_80+) ------------------
__device__ __forceinline__ void ldsm_x4(u32& r0,u32& r1,u32& r2,u32& r3, u32 addr){
    asm volatile("ldmatrix.sync.aligned.m8n8.x4.shared.b16 {%0,%1,%2,%3}, [%4];"
        : "=r"(r0),"=r"(r1),"=r"(r2),"=r"(r3) : "r"(addr));
}
__device__ __forceinline__ void ldsm_x4_t(u32& r0,u32& r1,u32& r2,u32& r3, u32 addr){
    asm volatile("ldmatrix.sync.aligned.m8n8.x4.trans.shared.b16 {%0,%1,%2,%3}, [%4];"
        : "=r"(r0),"=r"(r1),"=r"(r2),"=r"(r3) : "r"(addr));
}
__device__ __forceinline__ void mma_bf16(float* d, const u32* a, const u32* b){
    asm volatile("mma.sync.aligned.m16n8k16.row.col.f32.bf16.bf16.f32 "
        "{%0,%1,%2,%3}, {%4,%5,%6,%7}, {%8,%9}, {%0,%1,%2,%3};"
        : "+f"(d[0]),"+f"(d[1]),"+f"(d[2]),"+f"(d[3])
        : "r"(a[0]),"r"(a[1]),"r"(a[2]),"r"(a[3]), "r"(b[0]),"r"(b[1]));
}

// ---------------- scratch (device globals; no allocations) ----------------
// bf16 hi/lo, token-major [b][n][cs] as u32 (cs pairs)
__device__ __align__(16) u32 d_Qh[BB*NN*64];
__device__ __align__(16) u32 d_Ql[BB*NN*64];
__device__ __align__(16) u32 d_Kh[BB*NN*64];
__device__ __align__(16) u32 d_Kl[BB*NN*64];
__device__ __align__(16) u32 d_Vh[BB*NN*64];
__device__ __align__(16) u32 d_Vl[BB*NN*64];
__device__ float d_O[BB*NN*CSd];   // [b][n][cs]
__device__ float d_Y[BB*CC*NN];    // [b][c][n]
__device__ float d_scale[CC];
__device__ float d_shift[CC];

// ======================= Kernel A: QKV projections (FFMA2) =================
__global__ __launch_bounds__(256) void qkv_kernel(
    const float* __restrict__ x,
    const float* __restrict__ Wq, const float* __restrict__ bq,
    const float* __restrict__ Wk, const float* __restrict__ bk,
    const float* __restrict__ Wv, const float* __restrict__ bv)
{
    __shared__ float Ws[128*37];
    __shared__ float Xs[32*132];
    const int z  = blockIdx.z;
    const int b  = blockIdx.y;
    const int n0 = blockIdx.x * 128;
    const float* W    = (z==0) ? Wq : (z==1) ? Wk : Wv;
    const float* bias = (z==0) ? bq : (z==1) ? bk : bv;
    const int tid = threadIdx.x;
    const int ty = tid >> 4, tx = tid & 15;

    ull acc2[8][4];
    #pragma unroll
    for (int i = 0; i < 8; i++)
        #pragma unroll
        for (int j = 0; j < 4; j++) acc2[i][j] = 0ull;

    for (int k0 = 0; k0 < CC; k0 += 32) {
        #pragma unroll
        for (int it = 0; it < 16; it++) {
            int f = tid + it*256;
            Ws[(f>>5)*37 + (f&31)] = W[(f>>5)*CC + k0 + (f&31)];
        }
        #pragma unroll
        for (int it = 0; it < 16; it++) {
            int f = tid + it*256;
            Xs[(f>>7)*132 + (f&127)] = x[(b*CC + k0 + (f>>7))*NN + n0 + (f&127)];
        }
        __syncthreads();
        #pragma unroll 4
        for (int kc = 0; kc < 32; kc++) {
            ull ad[8];
            #pragma unroll
            for (int i = 0; i < 8; i++) {
                float a = Ws[(ty*8+i)*37 + kc];
                ad[i] = pack2(a, a);
            }
            ulonglong2 x0 = *(const ulonglong2*)&Xs[kc*132 + tx*8];
            ulonglong2 x1 = *(const ulonglong2*)&Xs[kc*132 + tx*8 + 4];
            ull bbv[4] = {x0.x, x0.y, x1.x, x1.y};
            #pragma unroll
            for (int i = 0; i < 8; i++)
                #pragma unroll
                for (int j = 0; j < 4; j++)
                    acc2[i][j] = ffma2(ad[i], bbv[j], acc2[i][j]);
        }
        __syncthreads();
    }

    float accf[8][8];
    #pragma unroll
    for (int i = 0; i < 8; i++)
        #pragma unroll
        for (int j = 0; j < 4; j++)
            unpack2(acc2[i][j], accf[i][2*j], accf[i][2*j+1]);
    float bl[8];
    #pragma unroll
    for (int i = 0; i < 8; i++) bl[i] = bias[ty*8 + i];

    u32* oh = (z==0) ? d_Qh : (z==1) ? d_Kh : d_Vh;
    u32* ol = (z==0) ? d_Ql : (z==1) ? d_Kl : d_Vl;
    #pragma unroll
    for (int j = 0; j < 8; j++) {
        int n = n0 + tx*8 + j;
        float v[8];
        #pragma unroll
        for (int i = 0; i < 8; i++) v[i] = accf[i][j] + bl[i];
        u32 h[4], l[4];
        #pragma unroll
        for (int t = 0; t < 4; t++) {
            h[t] = cvt_bf2(v[2*t+1], v[2*t]);
            float f1 = __uint_as_float(h[t] & 0xffff0000u);
            float f0 = __uint_as_float(h[t] << 16);
            l[t] = cvt_bf2(v[2*t+1]-f1, v[2*t]-f0);
        }
        size_t u = (size_t)(b*NN + n)*64 + ty*4;
        *(uint4*)&oh[u] = make_uint4(h[0],h[1],h[2],h[3]);
        *(uint4*)&ol[u] = make_uint4(l[0],l[1],l[2],l[3]);
    }
}

// ======================= Kernel B: HMMA flash attention =====================
// grid (32, B), 256 thr (8 warps x 16 q-rows). Smem: 6 tiles 128x136 bf16.
#define STB 272                      // row stride bytes (136 bf16)
#define TILE_BYTES (128*STB)         // 34816
#define OFF_QH 0
#define OFF_QL (1*TILE_BYTES)
#define OFF_KH (2*TILE_BYTES)
#define OFF_KL (3*TILE_BYTES)
#define OFF_VH (4*TILE_BYTES)
#define OFF_VL (5*TILE_BYTES)
#define ATTN_SMEM_BYTES (6*TILE_BYTES)

__global__ __launch_bounds__(256, 1) void attn_kernel()
{
    extern __shared__ __align__(16) char smem[];
    const u32 sb = smem_u32(smem);
    const int b  = blockIdx.y;
    const int q0 = blockIdx.x * 128;
    const int tid = threadIdx.x;
    const int w = tid >> 5, lane = tid & 31;
    const int g = lane >> 3, lr = lane & 7, quad = lane & 3;

    // ---- Q tile fill (hi/lo), rows=q, cols=dim ----
    #pragma unroll
    for (int i = 0; i < 16; i++) {
        int f = tid + i*256;              // 0..4095 uint4
        int sp = f >> 11, idx = f & 2047;
        int row = idx >> 4, c16 = idx & 15;
        const u32* src = (sp ? d_Ql : d_Qh) + (size_t)(b*NN + q0 + row)*64 + c16*4;
        *(uint4*)(smem + (sp ? OFF_QL : OFF_QH) + row*STB + c16*16) = *(const uint4*)src;
    }

    // ---- per-lane ldmatrix base addresses ----
    // A(Q): matrix g -> rows w*16+(g&1)*8+lr, col-offset (g>>1)*8 ; +ks*32B
    const u32 aQh = sb + OFF_QH + (u32)((w*16 + (g&1)*8 + lr)*STB + (g>>1)*16);
    const u32 aQl = aQh + TILE_BYTES;
    // B(K) non-trans: matrix g -> key rows n0+(g>>1)*8+lr, dim offset (g&1)*8 ; +nbp*16*STB + ks*32B
    const u32 aKoff = (u32)(((g>>1)*8 + lr)*STB + (g&1)*16);
    const u32 aKh = sb + OFF_KH + aKoff;
    const u32 aKl = sb + OFF_KL + aKoff;
    // B(V) trans: matrix g -> key rows k0+(g&1)*8+lr, dim offset (g>>1)*8 ; +ks2*16*STB + nbp*32B
    const u32 aVoff = (u32)(((g&1)*8 + lr)*STB + (g>>1)*16);
    const u32 aVh = sb + OFF_VH + aVoff;
    const u32 aVl = sb + OFF_VL + aVoff;

    float o[16][4];
    #pragma unroll
    for (int nb = 0; nb < 16; nb++)
        #pragma unroll
        for (int e = 0; e < 4; e++) o[nb][e] = 0.f;
    float m0 = -1e30f, m1 = -1e30f, l0 = 0.f, l1 = 0.f;

    for (int kt = 0; kt < NN/128; kt++) {
        const int kb = kt * 128;
        __syncthreads();                    // prev PV reads done
        // ---- fill K,V tiles (hi/lo), rows=key, cols=dim ----
        #pragma unroll
        for (int i = 0; i < 32; i++) {
            int f = tid + i*256;            // 0..8191 uint4
            int t4 = f >> 11, idx = f & 2047;
            int row = idx >> 4, c16 = idx & 15;
            size_t su = (size_t)(b*NN + kb + row)*64 + c16*4;
            const u32* src = (t4==0) ? d_Kh + su : (t4==1) ? d_Kl + su
                           : (t4==2) ? d_Vh + su : d_Vl + su;
            *(uint4*)(smem + OFF_KH + t4*TILE_BYTES + row*STB + c16*16) = *(const uint4*)src;
        }
        __syncthreads();

        // ---- S = Q.K^T (split: hh + hl + lh) ----
        float s[16][4];
        #pragma unroll
        for (int nb = 0; nb < 16; nb++)
            #pragma unroll
            for (int e = 0; e < 4; e++) s[nb][e] = 0.f;

        #pragma unroll
        for (int ks = 0; ks < 8; ks++) {
            u32 ah[4], al[4];
            ldsm_x4(ah[0],ah[1],ah[2],ah[3], aQh + ks*32);
            ldsm_x4(al[0],al[1],al[2],al[3], aQl + ks*32);
            #pragma unroll
            for (int nbp = 0; nbp < 8; nbp++) {
                u32 kh[4], kl[4];
                ldsm_x4(kh[0],kh[1],kh[2],kh[3], aKh + nbp*16*STB + ks*32);
                ldsm_x4(kl[0],kl[1],kl[2],kl[3], aKl + nbp*16*STB + ks*32);
                mma_bf16(s[2*nbp],   ah, &kh[0]);
                mma_bf16(s[2*nbp],   ah, &kl[0]);
                mma_bf16(s[2*nbp],   al, &kh[0]);
                mma_bf16(s[2*nbp+1], ah, &kh[2]);
                mma_bf16(s[2*nbp+1], ah, &kl[2]);
                mma_bf16(s[2*nbp+1], al, &kh[2]);
            }
        }

        // ---- online softmax (rows warp-private; quad shfl reduce) ----
        float tm0 = -1e30f, tm1 = -1e30f;
        #pragma unroll
        for (int nb = 0; nb < 16; nb++) {
            tm0 = fmaxf(tm0, fmaxf(s[nb][0], s[nb][1]));
            tm1 = fmaxf(tm1, fmaxf(s[nb][2], s[nb][3]));
        }
        tm0 = fmaxf(tm0, __shfl_xor_sync(0xffffffffu, tm0, 1));
        tm0 = fmaxf(tm0, __shfl_xor_sync(0xffffffffu, tm0, 2));
        tm1 = fmaxf(tm1, __shfl_xor_sync(0xffffffffu, tm1, 1));
        tm1 = fmaxf(tm1, __shfl_xor_sync(0xffffffffu, tm1, 2));
        float nm0 = fmaxf(m0, tm0), nm1 = fmaxf(m1, tm1);
        float rs0 = __expf(m0 - nm0), rs1 = __expf(m1 - nm1);
        m0 = nm0; m1 = nm1;
        float ps0 = 0.f, ps1 = 0.f;
        #pragma unroll
        for (int nb = 0; nb < 16; nb++) {
            s[nb][0] = __expf(s[nb][0] - nm0);
            s[nb][1] = __expf(s[nb][1] - nm0);
            s[nb][2] = __expf(s[nb][2] - nm1);
            s[nb][3] = __expf(s[nb][3] - nm1);
            ps0 += s[nb][0] + s[nb][1];
            ps1 += s[nb][2] + s[nb][3];
            o[nb][0] *= rs0; o[nb][1] *= rs0;
            o[nb][2] *= rs1; o[nb][3] *= rs1;
        }
        ps0 += __shfl_xor_sync(0xffffffffu, ps0, 1);
        ps0 += __shfl_xor_sync(0xffffffffu, ps0, 2);
        ps1 += __shfl_xor_sync(0xffffffffu, ps1, 1);
        ps1 += __shfl_xor_sync(0xffffffffu, ps1, 2);
        l0 = l0*rs0 + ps0;
        l1 = l1*rs1 + ps1;

        // ---- O += P.V (split: hh + hl + lh); P repacked from registers ----
        #pragma unroll
        for (int ks2 = 0; ks2 < 8; ks2++) {
            u32 pah[4], pal[4];
            pah[0] = cvt_bf2(s[2*ks2][1],   s[2*ks2][0]);
            pah[1] = cvt_bf2(s[2*ks2][3],   s[2*ks2][2]);
            pah[2] = cvt_bf2(s[2*ks2+1][1], s[2*ks2+1][0]);
            pah[3] = cvt_bf2(s[2*ks2+1][3], s[2*ks2+1][2]);
            #pragma unroll
            for (int u2 = 0; u2 < 4; u2++) {
                int nb = 2*ks2 + (u2 >> 1);
                int e  = (u2 & 1) * 2;
                float f0 = __uint_as_float(pah[u2] << 16);
                float f1 = __uint_as_float(pah[u2] & 0xffff0000u);
                pal[u2] = cvt_bf2(s[nb][e+1] - f1, s[nb][e] - f0);
            }
            #pragma unroll
            for (int nbp = 0; nbp < 8; nbp++) {
                u32 vh[4], vl[4];
                ldsm_x4_t(vh[0],vh[1],vh[2],vh[3], aVh + ks2*16*STB + nbp*32);
                ldsm_x4_t(vl[0],vl[1],vl[2],vl[3], aVl + ks2*16*STB + nbp*32);
                mma_bf16(o[2*nbp],   pah, &vh[0]);
                mma_bf16(o[2*nbp],   pah, &vl[0]);
                mma_bf16(o[2*nbp],   pal, &vh[0]);
                mma_bf16(o[2*nbp+1], pah, &vh[2]);
                mma_bf16(o[2*nbp+1], pah, &vl[2]);
                mma_bf16(o[2*nbp+1], pal, &vh[2]);
            }
        }
    }

    // ---- epilogue: normalize, write d_O[b][q][cs] ----
    float inv0 = 1.0f / l0, inv1 = 1.0f / l1;
    int r0g = q0 + w*16 + (lane >> 2), r1g = r0g + 8;
    #pragma unroll
    for (int nb = 0; nb < 16; nb++) {
        int cc2 = nb*8 + quad*2;
        *(float2*)&d_O[(size_t)(b*NN + r0g)*CSd + cc2] = make_float2(o[nb][0]*inv0, o[nb][1]*inv0);
        *(float2*)&d_O[(size_t)(b*NN + r1g)*CSd + cc2] = make_float2(o[nb][2]*inv1, o[nb][3]*inv1);
    }
}

// ======================= Kernel C: output projection (FFMA2) ===============
__global__ __launch_bounds__(256) void oproj_kernel(
    const float* __restrict__ Wo, const float* __restrict__ bo)
{
    __shared__ float Wos[128*37];
    __shared__ float Os[32*132];
    const int b  = blockIdx.z;
    const int c0 = blockIdx.y * 128;
    const int n0 = blockIdx.x * 128;
    const int tid = threadIdx.x;
    const int ty = tid >> 4, tx = tid & 15;

    ull acc2[8][4];
    #pragma unroll
    for (int i = 0; i < 8; i++)
        #pragma unroll
        for (int j = 0; j < 4; j++) acc2[i][j] = 0ull;

    for (int k0 = 0; k0 < CSd; k0 += 32) {
        #pragma unroll
        for (int it = 0; it < 16; it++) {
            int f = tid + it*256;
            Wos[(f>>5)*37 + (f&31)] = Wo[(c0 + (f>>5))*CSd + k0 + (f&31)];
        }
        #pragma unroll
        for (int it = 0; it < 16; it++) {
            int f = tid + it*256;
            Os[(f&31)*132 + (f>>5)] = d_O[(size_t)(b*NN + n0 + (f>>5))*CSd + k0 + (f&31)];
        }
        __syncthreads();
        #pragma unroll 4
        for (int kc = 0; kc < 32; kc++) {
            ull ad[8];
            #pragma unroll
            for (int i = 0; i < 8; i++) {
                float a = Wos[(ty*8+i)*37 + kc];
                ad[i] = pack2(a, a);
            }
            ulonglong2 x0 = *(const ulonglong2*)&Os[kc*132 + tx*8];
            ulonglong2 x1 = *(const ulonglong2*)&Os[kc*132 + tx*8 + 4];
            ull bbv[4] = {x0.x, x0.y, x1.x, x1.y};
            #pragma unroll
            for (int i = 0; i < 8; i++)
                #pragma unroll
                for (int j = 0; j < 4; j++)
                    acc2[i][j] = ffma2(ad[i], bbv[j], acc2[i][j]);
        }
        __syncthreads();
    }

    #pragma unroll
    for (int i = 0; i < 8; i++) {
        float accf[8];
        #pragma unroll
        for (int j = 0; j < 4; j++) unpack2(acc2[i][j], accf[2*j], accf[2*j+1]);
        int c = c0 + ty*8 + i;
        float bv2 = bo[c];
        float* p = &d_Y[(size_t)(b*CC + c)*NN + n0 + tx*8];
        *(float4*)p       = make_float4(accf[0]+bv2, accf[1]+bv2, accf[2]+bv2, accf[3]+bv2);
        *((float4*)p + 1) = make_float4(accf[4]+bv2, accf[5]+bv2, accf[6]+bv2, accf[7]+bv2);
    }
}

// ======================= Kernel D: BN stats =================================
__global__ __launch_bounds__(256) void bnstat_kernel(
    const float* __restrict__ gamma, const float* __restrict__ beta)
{
    __shared__ float rs[256], rs2[256];
    const int c = blockIdx.x, tid = threadIdx.x;
    float s = 0.f, s2 = 0.f;
    #pragma unroll 4
    for (int j = 0; j < 64; j++) {
        int idx = tid + j*256;
        int bb2 = idx >> 12, nn2 = idx & 4095;
        float v = d_Y[(size_t)(bb2*CC + c)*NN + nn2];
        s += v; s2 += v*v;
    }
    rs[tid] = s; rs2[tid] = s2;
    __syncthreads();
    for (int off = 128; off > 0; off >>= 1) {
        if (tid < off) { rs[tid] += rs[tid+off]; rs2[tid] += rs2[tid+off]; }
        __syncthreads();
    }
    if (tid == 0) {
        float mean = rs[0]  * (1.f/16384.f);
        float var  = rs2[0] * (1.f/16384.f) - mean*mean;
        float sc = gamma[c] * rsqrtf(var + EPSc);
        d_scale[c] = sc;
        d_shift[c] = beta[c] - mean*sc;
    }
}

// ======================= Kernel E: BN affine + ReLU + residual ==============
__global__ __launch_bounds__(256) void epilogue_kernel(
    const float* __restrict__ x, float* __restrict__ out)
{
    int i4 = blockIdx.x*256 + threadIdx.x;
    int idx = i4 * 4;
    int c = (idx >> 12) & 255;
    float sc = d_scale[c], sh = d_shift[c];
    float4 y   = *(const float4*)&d_Y[idx];
    float4 xin = ((const float4*)x)[i4];
    float4 r;
    r.x = fmaxf(fmaf(y.x, sc, sh), 0.f) + xin.x;
    r.y = fmaxf(fmaf(y.y, sc, sh), 0.f) + xin.y;
    r.z = fmaxf(fmaf(y.z, sc, sh), 0.f) + xin.z;
    r.w = fmaxf(fmaf(y.w, sc, sh), 0.f) + xin.w;
    ((float4*)out)[i4] = r;
}

// ============================ launch =======================================
extern "C" void kernel_launch(void* const* d_in, const int* in_sizes, int n_in,
                              void* d_out, int out_size)
{
    const float* x     = (const float*)d_in[0];
    const float* Wq    = (const float*)d_in[1];
    const float* bq    = (const float*)d_in[2];
    const float* Wk    = (const float*)d_in[3];
    const float* bk    = (const float*)d_in[4];
    const float* Wv    = (const float*)d_in[5];
    const float* bv    = (const float*)d_in[6];
    const float* Wo    = (const float*)d_in[7];
    const float* bo    = (const float*)d_in[8];
    const float* gamma = (const float*)d_in[9];
    const float* beta  = (const float*)d_in[10];
    float* out = (float*)d_out;

    cudaFuncSetAttribute(attn_kernel,
                         cudaFuncAttributeMaxDynamicSharedMemorySize,
                         ATTN_SMEM_BYTES);

    qkv_kernel<<<dim3(NN/128, BB, 3), 256>>>(x, Wq, bq, Wk, bk, Wv, bv);
    attn_kernel<<<dim3(NN/128, BB), 256, ATTN_SMEM_BYTES>>>();
    oproj_kernel<<<dim3(NN/128, CC/128, BB), 256>>>(Wo, bo);
    bnstat_kernel<<<CC, 256>>>(gamma, beta);
    epilogue_kernel<<<(BB*CC*NN)/4/256, 256>>>(x, out);
}

// round 7
// speedup vs baseline: 2.8340x; 1.1897x over previous
#include <cuda_runtime.h>
#include <math.h>
#include <stdint.h>

#define BB   4
#define CC   256
#define CSd  128
#define NN   4096
#define EPSc 1e-5f

typedef unsigned long long ull;
typedef unsigned int u32;

// ---------------- FFMA2 helpers ----------------
__device__ __forceinline__ ull pack2(float x, float y){
    ull r; asm("mov.b64 %0, {%1,%2};" : "=l"(r) : "f"(x), "f"(y)); return r;
}
__device__ __forceinline__ void unpack2(ull v, float& x, float& y){
    asm("mov.b64 {%0,%1}, %2;" : "=f"(x), "=f"(y) : "l"(v));
}
__device__ __forceinline__ ull ffma2(ull a, ull b, ull c){
    ull d; asm("fma.rn.f32x2 %0, %1, %2, %3;" : "=l"(d) : "l"(a), "l"(b), "l"(c)); return d;
}
// bf16x2 pack: low half = bf16(v0), high half = bf16(v1)
__device__ __forceinline__ u32 cvt_bf2(float v1, float v0){
    u32 r; asm("cvt.rn.bf16x2.f32 %0, %1, %2;" : "=r"(r) : "f"(v1), "f"(v0)); return r;
}
__device__ __forceinline__ u32 smem_u32(const void* p){
    u32 a; asm("{ .reg .u64 t; cvta.to.shared.u64 t, %1; cvt.u32.u64 %0, t; }" : "=r"(a) : "l"(p));
    return a;
}

// ---------------- warp-MMA + cp.async helpers ------------------------------
__device__ __forceinline__ void ldsm_x4(u32& r0,u32& r1,u32& r2,u32& r3, u32 addr){
    asm volatile("ldmatrix.sync.aligned.m8n8.x4.shared.b16 {%0,%1,%2,%3}, [%4];"
        : "=r"(r0),"=r"(r1),"=r"(r2),"=r"(r3) : "r"(addr));
}
__device__ __forceinline__ void ldsm_x4_t(u32& r0,u32& r1,u32& r2,u32& r3, u32 addr){
    asm volatile("ldmatrix.sync.aligned.m8n8.x4.trans.shared.b16 {%0,%1,%2,%3}, [%4];"
        : "=r"(r0),"=r"(r1),"=r"(r2),"=r"(r3) : "r"(addr));
}
__device__ __forceinline__ void mma_bf16(float* d, const u32* a, const u32* b){
    asm volatile("mma.sync.aligned.m16n8k16.row.col.f32.bf16.bf16.f32 "
        "{%0,%1,%2,%3}, {%4,%5,%6,%7}, {%8,%9}, {%0,%1,%2,%3};"
        : "+f"(d[0]),"+f"(d[1]),"+f"(d[2]),"+f"(d[3])
        : "r"(a[0]),"r"(a[1]),"r"(a[2]),"r"(a[3]), "r"(b[0]),"r"(b[1]));
}
#define CP16(dst, src)  asm volatile("cp.async.cg.shared.global [%0], [%1], 16;" :: "r"(dst), "l"(src))
#define CP_COMMIT()     asm volatile("cp.async.commit_group;" ::: "memory")
#define CP_WAIT1()      asm volatile("cp.async.wait_group 1;" ::: "memory")

// ---------------- scratch (device globals; no allocations) ----------------
// bf16 hi/lo, token-major [b][n][cs] as u32 (cs pairs)
__device__ __align__(16) u32 d_Qh[BB*NN*64];
__device__ __align__(16) u32 d_Ql[BB*NN*64];
__device__ __align__(16) u32 d_Kh[BB*NN*64];
__device__ __align__(16) u32 d_Kl[BB*NN*64];
__device__ __align__(16) u32 d_Vh[BB*NN*64];
__device__ __align__(16) u32 d_Vl[BB*NN*64];
// x transposed+split: [b][n][c] as u32 (c pairs)
__device__ __align__(16) u32 d_xh[BB*NN*128];
__device__ __align__(16) u32 d_xl[BB*NN*128];
// W split: [z][cs][c/2]
__device__ __align__(16) u32 d_Wh[3*CSd*128];
__device__ __align__(16) u32 d_Wl[3*CSd*128];
__device__ float d_O[BB*NN*CSd];   // [b][n][cs]
__device__ float d_Y[BB*CC*NN];    // [b][c][n]
__device__ float d_scale[CC];
__device__ float d_shift[CC];

// ======================= Prep 1: W split ====================================
__global__ __launch_bounds__(256) void wsplit_kernel(
    const float* __restrict__ Wq, const float* __restrict__ Wk,
    const float* __restrict__ Wv)
{
    const int z = blockIdx.y;
    const float* W = (z==0) ? Wq : (z==1) ? Wk : Wv;
    #pragma unroll
    for (int it = 0; it < 8; it++) {
        int i = blockIdx.x*2048 + threadIdx.x + it*256;   // 0..16383
        int cs = i >> 7, jp = i & 127;
        float v0 = W[cs*CC + 2*jp], v1 = W[cs*CC + 2*jp + 1];
        u32 h = cvt_bf2(v1, v0);
        float f1 = __uint_as_float(h & 0xffff0000u);
        float f0 = __uint_as_float(h << 16);
        d_Wh[z*16384 + i] = h;
        d_Wl[z*16384 + i] = cvt_bf2(v1 - f1, v0 - f0);
    }
}

// ======================= Prep 2: x transpose + split ========================
// grid (NN/64, CC/64, B). smem tile 64c x 64n.
__global__ __launch_bounds__(256) void xsplit_kernel(const float* __restrict__ x)
{
    __shared__ float t[64*65];
    const int b  = blockIdx.z;
    const int c0 = blockIdx.y * 64;
    const int n0 = blockIdx.x * 64;
    const int tid = threadIdx.x;
    #pragma unroll
    for (int it = 0; it < 16; it++) {
        int idx = tid + it*256;           // 0..4095
        int r = idx >> 6, col = idx & 63;
        t[r*65 + col] = x[(size_t)(b*CC + c0 + r)*NN + n0 + col];
    }
    __syncthreads();
    #pragma unroll
    for (int it = 0; it < 8; it++) {
        int idx = tid + it*256;           // 0..2047
        int nl = idx >> 5, jp = idx & 31;
        float v0 = t[(2*jp)*65 + nl], v1 = t[(2*jp+1)*65 + nl];
        u32 h = cvt_bf2(v1, v0);
        float f1 = __uint_as_float(h & 0xffff0000u);
        float f0 = __uint_as_float(h << 16);
        size_t u = (size_t)(b*NN + n0 + nl)*128 + (c0 >> 1) + jp;
        d_xh[u] = h;
        d_xl[u] = cvt_bf2(v1 - f1, v0 - f0);
    }
}

// ======================= Kernel A: QKV projections (HMMA) ===================
// grid (N/128, B, 3z), 8 warps. C[n 128][cs 128] = xT[n][c] . W[cs][c]^T, k=256
#define STB 272                       // row stride bytes (136 bf16)
#define TILE_B 34816                  // 128*272
#define QKV_SMEM (4*TILE_B)           // Ah,Al,Bh,Bl (one 128-k chunk)

__global__ __launch_bounds__(256, 1) void qkv_kernel(
    const float* __restrict__ bq, const float* __restrict__ bk,
    const float* __restrict__ bv)
{
    extern __shared__ __align__(16) char smem[];
    const u32 sb = smem_u32(smem);
    const int z  = blockIdx.z;
    const int b  = blockIdx.y;
    const int n0 = blockIdx.x * 128;
    const float* bias = (z==0) ? bq : (z==1) ? bk : bv;
    const int tid = threadIdx.x;
    const int w = tid >> 5, lane = tid & 31;
    const int g = lane >> 3, lr = lane & 7, quad = lane & 3;

    const u32 aA = sb + (u32)((w*16 + (g&1)*8 + lr)*STB + (g>>1)*16);
    const u32 aB = sb + 2*TILE_B + (u32)(((g>>1)*8 + lr)*STB + (g&1)*16);

    float acc[16][4];
    #pragma unroll
    for (int nb = 0; nb < 16; nb++)
        #pragma unroll
        for (int e = 0; e < 4; e++) acc[nb][e] = 0.f;

    for (int ch = 0; ch < 2; ch++) {
        __syncthreads();
        #pragma unroll
        for (int i = 0; i < 32; i++) {
            int f = tid + i*256;            // 0..8191 uint4
            int t4 = f >> 11, idx = f & 2047;
            int row = idx >> 4, c16 = idx & 15;
            const u32* src;
            if (t4 < 2)
                src = (t4 ? d_xl : d_xh) + (size_t)(b*NN + n0 + row)*128 + ch*64 + c16*4;
            else
                src = ((t4==2) ? d_Wh : d_Wl) + (size_t)(z*CSd + row)*128 + ch*64 + c16*4;
            *(uint4*)(smem + t4*TILE_B + row*STB + c16*16) = *(const uint4*)src;
        }
        __syncthreads();
        #pragma unroll
        for (int ks = 0; ks < 8; ks++) {
            u32 ah[4], al[4];
            ldsm_x4(ah[0],ah[1],ah[2],ah[3], aA + ks*32);
            ldsm_x4(al[0],al[1],al[2],al[3], aA + TILE_B + ks*32);
            #pragma unroll
            for (int nbp = 0; nbp < 8; nbp++) {
                u32 bh[4], blo[4];
                ldsm_x4(bh[0],bh[1],bh[2],bh[3],   aB + nbp*16*STB + ks*32);
                ldsm_x4(blo[0],blo[1],blo[2],blo[3], aB + TILE_B + nbp*16*STB + ks*32);
                mma_bf16(acc[2*nbp],   ah, &bh[0]);
                mma_bf16(acc[2*nbp],   ah, &blo[0]);
                mma_bf16(acc[2*nbp],   al, &bh[0]);
                mma_bf16(acc[2*nbp+1], ah, &bh[2]);
                mma_bf16(acc[2*nbp+1], ah, &blo[2]);
                mma_bf16(acc[2*nbp+1], al, &bh[2]);
            }
        }
    }

    u32* oh = (z==0) ? d_Qh : (z==1) ? d_Kh : d_Vh;
    u32* ol = (z==0) ? d_Ql : (z==1) ? d_Kl : d_Vl;
    int r0 = n0 + w*16 + (lane >> 2);
    #pragma unroll
    for (int nb = 0; nb < 16; nb++) {
        int col = nb*8 + quad*2;
        float b0 = __ldg(&bias[col]), b1 = __ldg(&bias[col+1]);
        #pragma unroll
        for (int half = 0; half < 2; half++) {
            float v0 = acc[nb][2*half]   + b0;
            float v1 = acc[nb][2*half+1] + b1;
            u32 h = cvt_bf2(v1, v0);
            float f1 = __uint_as_float(h & 0xffff0000u);
            float f0 = __uint_as_float(h << 16);
            size_t u = (size_t)(b*NN + r0 + half*8)*64 + nb*4 + quad;
            oh[u] = h;
            ol[u] = cvt_bf2(v1 - f1, v0 - f0);
        }
    }
}

// ======================= Kernel B: HMMA flash attention (cp.async) ==========
#define OFF_QH 0
#define OFF_QL (1*TILE_B)
#define OFF_KH (2*TILE_B)
#define OFF_KL (3*TILE_B)
#define OFF_VH (4*TILE_B)
#define OFF_VL (5*TILE_B)
#define ATTN_SMEM_BYTES (6*TILE_B)

__device__ __forceinline__ void issue_kv(u32 sb, int tid, int b, int kb,
                                         int voff, const u32* ph, const u32* pl)
{
    #pragma unroll
    for (int i = 0; i < 16; i++) {
        int f = tid + i*256;               // 0..4095 uint4
        int sp = f >> 11, idx = f & 2047;
        int row = idx >> 4, c16 = idx & 15;
        const u32* src = (sp ? pl : ph) + (size_t)(b*NN + kb + row)*64 + c16*4;
        CP16(sb + (u32)(voff + sp*TILE_B + row*STB + c16*16), src);
    }
}

__global__ __launch_bounds__(256, 1) void attn_kernel()
{
    extern __shared__ __align__(16) char smem[];
    const u32 sb = smem_u32(smem);
    const int b  = blockIdx.y;
    const int q0 = blockIdx.x * 128;
    const int tid = threadIdx.x;
    const int w = tid >> 5, lane = tid & 31;
    const int g = lane >> 3, lr = lane & 7, quad = lane & 3;

    // Q tile fill (regular loads, once)
    #pragma unroll
    for (int i = 0; i < 16; i++) {
        int f = tid + i*256;
        int sp = f >> 11, idx = f & 2047;
        int row = idx >> 4, c16 = idx & 15;
        const u32* src = (sp ? d_Ql : d_Qh) + (size_t)(b*NN + q0 + row)*64 + c16*4;
        *(uint4*)(smem + (sp ? OFF_QL : OFF_QH) + row*STB + c16*16) = *(const uint4*)src;
    }

    const u32 aQh = sb + OFF_QH + (u32)((w*16 + (g&1)*8 + lr)*STB + (g>>1)*16);
    const u32 aQl = aQh + TILE_B;
    const u32 aKoff = (u32)(((g>>1)*8 + lr)*STB + (g&1)*16);
    const u32 aKh = sb + OFF_KH + aKoff;
    const u32 aKl = sb + OFF_KL + aKoff;
    const u32 aVoff = (u32)(((g&1)*8 + lr)*STB + (g>>1)*16);
    const u32 aVh = sb + OFF_VH + aVoff;
    const u32 aVl = sb + OFF_VL + aVoff;

    float o[16][4];
    #pragma unroll
    for (int nb = 0; nb < 16; nb++)
        #pragma unroll
        for (int e = 0; e < 4; e++) o[nb][e] = 0.f;
    float m0 = -1e30f, m1 = -1e30f, l0 = 0.f, l1 = 0.f;

    // prologue: prefetch K(0), V(0)
    issue_kv(sb, tid, b, 0, OFF_KH, d_Kh, d_Kl); CP_COMMIT();
    issue_kv(sb, tid, b, 0, OFF_VH, d_Vh, d_Vl); CP_COMMIT();

    for (int kt = 0; kt < NN/128; kt++) {
        CP_WAIT1();                 // K(kt) ready
        __syncthreads();

        // ---- S = Q.K^T (hh + hl + lh) ----
        float s[16][4];
        #pragma unroll
        for (int nb = 0; nb < 16; nb++)
            #pragma unroll
            for (int e = 0; e < 4; e++) s[nb][e] = 0.f;
        #pragma unroll
        for (int ks = 0; ks < 8; ks++) {
            u32 ah[4], al[4];
            ldsm_x4(ah[0],ah[1],ah[2],ah[3], aQh + ks*32);
            ldsm_x4(al[0],al[1],al[2],al[3], aQl + ks*32);
            #pragma unroll
            for (int nbp = 0; nbp < 8; nbp++) {
                u32 kh[4], kl[4];
                ldsm_x4(kh[0],kh[1],kh[2],kh[3], aKh + nbp*16*STB + ks*32);
                ldsm_x4(kl[0],kl[1],kl[2],kl[3], aKl + nbp*16*STB + ks*32);
                mma_bf16(s[2*nbp],   ah, &kh[0]);
                mma_bf16(s[2*nbp],   ah, &kl[0]);
                mma_bf16(s[2*nbp],   al, &kh[0]);
                mma_bf16(s[2*nbp+1], ah, &kh[2]);
                mma_bf16(s[2*nbp+1], ah, &kl[2]);
                mma_bf16(s[2*nbp+1], al, &kh[2]);
            }
        }
        __syncthreads();            // all warps done reading K
        if (kt + 1 < NN/128)
            issue_kv(sb, tid, b, (kt+1)*128, OFF_KH, d_Kh, d_Kl);
        CP_COMMIT();

        // ---- online softmax (registers only) ----
        float tm0 = -1e30f, tm1 = -1e30f;
        #pragma unroll
        for (int nb = 0; nb < 16; nb++) {
            tm0 = fmaxf(tm0, fmaxf(s[nb][0], s[nb][1]));
            tm1 = fmaxf(tm1, fmaxf(s[nb][2], s[nb][3]));
        }
        tm0 = fmaxf(tm0, __shfl_xor_sync(0xffffffffu, tm0, 1));
        tm0 = fmaxf(tm0, __shfl_xor_sync(0xffffffffu, tm0, 2));
        tm1 = fmaxf(tm1, __shfl_xor_sync(0xffffffffu, tm1, 1));
        tm1 = fmaxf(tm1, __shfl_xor_sync(0xffffffffu, tm1, 2));
        float nm0 = fmaxf(m0, tm0), nm1 = fmaxf(m1, tm1);
        float rs0 = __expf(m0 - nm0), rs1 = __expf(m1 - nm1);
        m0 = nm0; m1 = nm1;
        float ps0 = 0.f, ps1 = 0.f;
        #pragma unroll
        for (int nb = 0; nb < 16; nb++) {
            s[nb][0] = __expf(s[nb][0] - nm0);
            s[nb][1] = __expf(s[nb][1] - nm0);
            s[nb][2] = __expf(s[nb][2] - nm1);
            s[nb][3] = __expf(s[nb][3] - nm1);
            ps0 += s[nb][0] + s[nb][1];
            ps1 += s[nb][2] + s[nb][3];
            o[nb][0] *= rs0; o[nb][1] *= rs0;
            o[nb][2] *= rs1; o[nb][3] *= rs1;
        }
        ps0 += __shfl_xor_sync(0xffffffffu, ps0, 1);
        ps0 += __shfl_xor_sync(0xffffffffu, ps0, 2);
        ps1 += __shfl_xor_sync(0xffffffffu, ps1, 1);
        ps1 += __shfl_xor_sync(0xffffffffu, ps1, 2);
        l0 = l0*rs0 + ps0;
        l1 = l1*rs1 + ps1;

        CP_WAIT1();                 // V(kt) ready (K(kt+1) in flight)
        __syncthreads();

        // ---- O += P.V (hh + hl + lh) ----
        #pragma unroll
        for (int ks2 = 0; ks2 < 8; ks2++) {
            u32 pah[4], pal[4];
            pah[0] = cvt_bf2(s[2*ks2][1],   s[2*ks2][0]);
            pah[1] = cvt_bf2(s[2*ks2][3],   s[2*ks2][2]);
            pah[2] = cvt_bf2(s[2*ks2+1][1], s[2*ks2+1][0]);
            pah[3] = cvt_bf2(s[2*ks2+1][3], s[2*ks2+1][2]);
            #pragma unroll
            for (int u2 = 0; u2 < 4; u2++) {
                int nb = 2*ks2 + (u2 >> 1);
                int e  = (u2 & 1) * 2;
                float f0 = __uint_as_float(pah[u2] << 16);
                float f1 = __uint_as_float(pah[u2] & 0xffff0000u);
                pal[u2] = cvt_bf2(s[nb][e+1] - f1, s[nb][e] - f0);
            }
            #pragma unroll
            for (int nbp = 0; nbp < 8; nbp++) {
                u32 vh[4], vl[4];
                ldsm_x4_t(vh[0],vh[1],vh[2],vh[3], aVh + ks2*16*STB + nbp*32);
                ldsm_x4_t(vl[0],vl[1],vl[2],vl[3], aVl + ks2*16*STB + nbp*32);
                mma_bf16(o[2*nbp],   pah, &vh[0]);
                mma_bf16(o[2*nbp],   pah, &vl[0]);
                mma_bf16(o[2*nbp],   pal, &vh[0]);
                mma_bf16(o[2*nbp+1], pah, &vh[2]);
                mma_bf16(o[2*nbp+1], pah, &vl[2]);
                mma_bf16(o[2*nbp+1], pal, &vh[2]);
            }
        }
        __syncthreads();            // all warps done reading V
        if (kt + 1 < NN/128)
            issue_kv(sb, tid, b, (kt+1)*128, OFF_VH, d_Vh, d_Vl);
        CP_COMMIT();
    }

    float inv0 = 1.0f / l0, inv1 = 1.0f / l1;
    int r0g = q0 + w*16 + (lane >> 2), r1g = r0g + 8;
    #pragma unroll
    for (int nb = 0; nb < 16; nb++) {
        int cc2 = nb*8 + quad*2;
        *(float2*)&d_O[(size_t)(b*NN + r0g)*CSd + cc2] = make_float2(o[nb][0]*inv0, o[nb][1]*inv0);
        *(float2*)&d_O[(size_t)(b*NN + r1g)*CSd + cc2] = make_float2(o[nb][2]*inv1, o[nb][3]*inv1);
    }
}

// ======================= Kernel C: output projection (FFMA2) ===============
__global__ __launch_bounds__(256) void oproj_kernel(
    const float* __restrict__ Wo, const float* __restrict__ bo)
{
    __shared__ float Wos[128*37];
    __shared__ float Os[32*132];
    const int b  = blockIdx.z;
    const int c0 = blockIdx.y * 128;
    const int n0 = blockIdx.x * 128;
    const int tid = threadIdx.x;
    const int ty = tid >> 4, tx = tid & 15;

    ull acc2[8][4];
    #pragma unroll
    for (int i = 0; i < 8; i++)
        #pragma unroll
        for (int j = 0; j < 4; j++) acc2[i][j] = 0ull;

    for (int k0 = 0; k0 < CSd; k0 += 32) {
        #pragma unroll
        for (int it = 0; it < 16; it++) {
            int f = tid + it*256;
            Wos[(f>>5)*37 + (f&31)] = Wo[(c0 + (f>>5))*CSd + k0 + (f&31)];
        }
        #pragma unroll
        for (int it = 0; it < 16; it++) {
            int f = tid + it*256;
            Os[(f&31)*132 + (f>>5)] = d_O[(size_t)(b*NN + n0 + (f>>5))*CSd + k0 + (f&31)];
        }
        __syncthreads();
        #pragma unroll 4
        for (int kc = 0; kc < 32; kc++) {
            ull ad[8];
            #pragma unroll
            for (int i = 0; i < 8; i++) {
                float a = Wos[(ty*8+i)*37 + kc];
                ad[i] = pack2(a, a);
            }
            ulonglong2 x0 = *(const ulonglong2*)&Os[kc*132 + tx*8];
            ulonglong2 x1 = *(const ulonglong2*)&Os[kc*132 + tx*8 + 4];
            ull bbv[4] = {x0.x, x0.y, x1.x, x1.y};
            #pragma unroll
            for (int i = 0; i < 8; i++)
                #pragma unroll
                for (int j = 0; j < 4; j++)
                    acc2[i][j] = ffma2(ad[i], bbv[j], acc2[i][j]);
        }
        __syncthreads();
    }

    #pragma unroll
    for (int i = 0; i < 8; i++) {
        float accf[8];
        #pragma unroll
        for (int j = 0; j < 4; j++) unpack2(acc2[i][j], accf[2*j], accf[2*j+1]);
        int c = c0 + ty*8 + i;
        float bv2 = bo[c];
        float* p = &d_Y[(size_t)(b*CC + c)*NN + n0 + tx*8];
        *(float4*)p       = make_float4(accf[0]+bv2, accf[1]+bv2, accf[2]+bv2, accf[3]+bv2);
        *((float4*)p + 1) = make_float4(accf[4]+bv2, accf[5]+bv2, accf[6]+bv2, accf[7]+bv2);
    }
}

// ======================= Kernel D: BN stats =================================
__global__ __launch_bounds__(256) void bnstat_kernel(
    const float* __restrict__ gamma, const float* __restrict__ beta)
{
    __shared__ float rs[256], rs2[256];
    const int c = blockIdx.x, tid = threadIdx.x;
    float s = 0.f, s2 = 0.f;
    #pragma unroll 4
    for (int j = 0; j < 64; j++) {
        int idx = tid + j*256;
        int bb2 = idx >> 12, nn2 = idx & 4095;
        float v = d_Y[(size_t)(bb2*CC + c)*NN + nn2];
        s += v; s2 += v*v;
    }
    rs[tid] = s; rs2[tid] = s2;
    __syncthreads();
    for (int off = 128; off > 0; off >>= 1) {
        if (tid < off) { rs[tid] += rs[tid+off]; rs2[tid] += rs2[tid+off]; }
        __syncthreads();
    }
    if (tid == 0) {
        float mean = rs[0]  * (1.f/16384.f);
        float var  = rs2[0] * (1.f/16384.f) - mean*mean;
        float sc = gamma[c] * rsqrtf(var + EPSc);
        d_scale[c] = sc;
        d_shift[c] = beta[c] - mean*sc;
    }
}

// ======================= Kernel E: BN affine + ReLU + residual ==============
__global__ __launch_bounds__(256) void epilogue_kernel(
    const float* __restrict__ x, float* __restrict__ out)
{
    int i4 = blockIdx.x*256 + threadIdx.x;
    int idx = i4 * 4;
    int c = (idx >> 12) & 255;
    float sc = d_scale[c], sh = d_shift[c];
    float4 y   = *(const float4*)&d_Y[idx];
    float4 xin = ((const float4*)x)[i4];
    float4 r;
    r.x = fmaxf(fmaf(y.x, sc, sh), 0.f) + xin.x;
    r.y = fmaxf(fmaf(y.y, sc, sh), 0.f) + xin.y;
    r.z = fmaxf(fmaf(y.z, sc, sh), 0.f) + xin.z;
    r.w = fmaxf(fmaf(y.w, sc, sh), 0.f) + xin.w;
    ((float4*)out)[i4] = r;
}

// ============================ launch =======================================
extern "C" void kernel_launch(void* const* d_in, const int* in_sizes, int n_in,
                              void* d_out, int out_size)
{
    const float* x     = (const float*)d_in[0];
    const float* Wq    = (const float*)d_in[1];
    const float* bq    = (const float*)d_in[2];
    const float* Wk    = (const float*)d_in[3];
    const float* bk    = (const float*)d_in[4];
    const float* Wv    = (const float*)d_in[5];
    const float* bv    = (const float*)d_in[6];
    const float* Wo    = (const float*)d_in[7];
    const float* bo    = (const float*)d_in[8];
    const float* gamma = (const float*)d_in[9];
    const float* beta  = (const float*)d_in[10];
    float* out = (float*)d_out;

    cudaFuncSetAttribute(attn_kernel,
                         cudaFuncAttributeMaxDynamicSharedMemorySize,
                         ATTN_SMEM_BYTES);
    cudaFuncSetAttribute(qkv_kernel,
                         cudaFuncAttributeMaxDynamicSharedMemorySize,
                         QKV_SMEM);

    wsplit_kernel<<<dim3(8, 3), 256>>>(Wq, Wk, Wv);
    xsplit_kernel<<<dim3(NN/64, CC/64, BB), 256>>>(x);
    qkv_kernel<<<dim3(NN/128, BB, 3), 256, QKV_SMEM>>>(bq, bk, bv);
    attn_kernel<<<dim3(NN/128, BB), 256, ATTN_SMEM_BYTES>>>();
    oproj_kernel<<<dim3(NN/128, CC/128, BB), 256>>>(Wo, bo);
    bnstat_kernel<<<CC, 256>>>(gamma, beta);
    epilogue_kernel<<<(BB*CC*NN)/4/256, 256>>>(x, out);
}

// round 8
// speedup vs baseline: 3.0113x; 1.0626x over previous
#include <cuda_runtime.h>
#include <math.h>
#include <stdint.h>

#define BB   4
#define CC   256
#define CSd  128
#define NN   4096
#define EPSc 1e-5f
#define LOG2E 1.4426950408889634f

typedef unsigned long long ull;
typedef unsigned int u32;

// ---------------- FFMA2 / misc helpers ----------------
__device__ __forceinline__ ull pack2(float x, float y){
    ull r; asm("mov.b64 %0, {%1,%2};" : "=l"(r) : "f"(x), "f"(y)); return r;
}
__device__ __forceinline__ void unpack2(ull v, float& x, float& y){
    asm("mov.b64 {%0,%1}, %2;" : "=f"(x), "=f"(y) : "l"(v));
}
__device__ __forceinline__ ull ffma2(ull a, ull b, ull c){
    ull d; asm("fma.rn.f32x2 %0, %1, %2, %3;" : "=l"(d) : "l"(a), "l"(b), "l"(c)); return d;
}
__device__ __forceinline__ u32 cvt_bf2(float v1, float v0){
    u32 r; asm("cvt.rn.bf16x2.f32 %0, %1, %2;" : "=r"(r) : "f"(v1), "f"(v0)); return r;
}
__device__ __forceinline__ float ex2f(float x){
    float r; asm("ex2.approx.f32 %0, %1;" : "=f"(r) : "f"(x)); return r;
}
__device__ __forceinline__ u32 smem_u32(const void* p){
    u32 a; asm("{ .reg .u64 t; cvta.to.shared.u64 t, %1; cvt.u32.u64 %0, t; }" : "=r"(a) : "l"(p));
    return a;
}

// ---------------- warp-MMA + cp.async helpers ------------------------------
__device__ __forceinline__ void ldsm_x4(u32& r0,u32& r1,u32& r2,u32& r3, u32 addr){
    asm volatile("ldmatrix.sync.aligned.m8n8.x4.shared.b16 {%0,%1,%2,%3}, [%4];"
        : "=r"(r0),"=r"(r1),"=r"(r2),"=r"(r3) : "r"(addr));
}
__device__ __forceinline__ void ldsm_x4_t(u32& r0,u32& r1,u32& r2,u32& r3, u32 addr){
    asm volatile("ldmatrix.sync.aligned.m8n8.x4.trans.shared.b16 {%0,%1,%2,%3}, [%4];"
        : "=r"(r0),"=r"(r1),"=r"(r2),"=r"(r3) : "r"(addr));
}
__device__ __forceinline__ void mma_bf16(float* d, const u32* a, const u32* b){
    asm volatile("mma.sync.aligned.m16n8k16.row.col.f32.bf16.bf16.f32 "
        "{%0,%1,%2,%3}, {%4,%5,%6,%7}, {%8,%9}, {%0,%1,%2,%3};"
        : "+f"(d[0]),"+f"(d[1]),"+f"(d[2]),"+f"(d[3])
        : "r"(a[0]),"r"(a[1]),"r"(a[2]),"r"(a[3]), "r"(b[0]),"r"(b[1]));
}
#define CP16(dst, src)  asm volatile("cp.async.cg.shared.global [%0], [%1], 16;" :: "r"(dst), "l"(src))
#define CP_COMMIT()     asm volatile("cp.async.commit_group;" ::: "memory")
#define CP_WAIT1()      asm volatile("cp.async.wait_group 1;" ::: "memory")

// ---------------- scratch (device globals; no allocations) ----------------
__device__ __align__(16) u32 d_Qh[BB*NN*64];   // bf16 [b][n][cs] pairs
__device__ __align__(16) u32 d_Ql[BB*NN*64];
__device__ __align__(16) u32 d_Kh[BB*NN*64];
__device__ __align__(16) u32 d_Kl[BB*NN*64];
__device__ __align__(16) u32 d_Vh[BB*NN*64];
__device__ __align__(16) u32 d_Vl[BB*NN*64];
__device__ __align__(16) u32 d_Oh[BB*NN*64];   // attention output splits
__device__ __align__(16) u32 d_Ol[BB*NN*64];
__device__ __align__(16) u32 d_xh[BB*NN*128];  // x transposed+split [b][n][c] pairs
__device__ __align__(16) u32 d_xl[BB*NN*128];
__device__ __align__(16) u32 d_Wh[3*CSd*128];  // W q/k/v splits [z][cs][c/2]
__device__ __align__(16) u32 d_Wl[3*CSd*128];
__device__ __align__(16) u32 d_Woh[CC*64];     // Wo splits [c][cs/2]
__device__ __align__(16) u32 d_Wol[CC*64];
__device__ float d_Y[BB*CC*NN];                // [b][c][n]
__device__ float d_ps1[128*CC];                // per-(b,ntile) channel sums
__device__ float d_ps2[128*CC];
__device__ float d_scale[CC];
__device__ float d_shift[CC];

// ======================= Prep 1: weight splits ==============================
__global__ __launch_bounds__(256) void wsplit_kernel(
    const float* __restrict__ Wq, const float* __restrict__ Wk,
    const float* __restrict__ Wv, const float* __restrict__ Wo)
{
    const int z = blockIdx.y;
    #pragma unroll
    for (int it = 0; it < 8; it++) {
        int i = blockIdx.x*2048 + threadIdx.x + it*256;   // 0..16383
        float v0, v1;
        if (z < 3) {
            const float* W = (z==0) ? Wq : (z==1) ? Wk : Wv;
            int cs = i >> 7, jp = i & 127;
            v0 = W[cs*CC + 2*jp]; v1 = W[cs*CC + 2*jp + 1];
        } else {
            int c = i >> 6, jp = i & 63;
            v0 = Wo[c*CSd + 2*jp]; v1 = Wo[c*CSd + 2*jp + 1];
        }
        u32 h = cvt_bf2(v1, v0);
        float f1 = __uint_as_float(h & 0xffff0000u);
        float f0 = __uint_as_float(h << 16);
        u32 l = cvt_bf2(v1 - f1, v0 - f0);
        if (z < 3) { d_Wh[z*16384 + i] = h; d_Wl[z*16384 + i] = l; }
        else       { d_Woh[i] = h;          d_Wol[i] = l; }
    }
}

// ======================= Prep 2: x transpose + split ========================
__global__ __launch_bounds__(256) void xsplit_kernel(const float* __restrict__ x)
{
    __shared__ float t[64*65];
    const int b  = blockIdx.z;
    const int c0 = blockIdx.y * 64;
    const int n0 = blockIdx.x * 64;
    const int tid = threadIdx.x;
    #pragma unroll
    for (int it = 0; it < 16; it++) {
        int idx = tid + it*256;
        int r = idx >> 6, col = idx & 63;
        t[r*65 + col] = x[(size_t)(b*CC + c0 + r)*NN + n0 + col];
    }
    __syncthreads();
    #pragma unroll
    for (int it = 0; it < 8; it++) {
        int idx = tid + it*256;
        int nl = idx >> 5, jp = idx & 31;
        float v0 = t[(2*jp)*65 + nl], v1 = t[(2*jp+1)*65 + nl];
        u32 h = cvt_bf2(v1, v0);
        float f1 = __uint_as_float(h & 0xffff0000u);
        float f0 = __uint_as_float(h << 16);
        size_t u = (size_t)(b*NN + n0 + nl)*128 + (c0 >> 1) + jp;
        d_xh[u] = h;
        d_xl[u] = cvt_bf2(v1 - f1, v0 - f0);
    }
}

// ======================= Kernel A: QKV projections (HMMA) ===================
#define STB 272
#define TILE_B 34816
#define QKV_SMEM (4*TILE_B)

__global__ __launch_bounds__(256, 1) void qkv_kernel(
    const float* __restrict__ bq, const float* __restrict__ bk,
    const float* __restrict__ bv)
{
    extern __shared__ __align__(16) char smem[];
    const u32 sb = smem_u32(smem);
    const int z  = blockIdx.z;
    const int b  = blockIdx.y;
    const int n0 = blockIdx.x * 128;
    const float* bias = (z==0) ? bq : (z==1) ? bk : bv;
    const float qsc = (z==0) ? LOG2E : 1.0f;
    const int tid = threadIdx.x;
    const int w = tid >> 5, lane = tid & 31;
    const int g = lane >> 3, lr = lane & 7, quad = lane & 3;

    const u32 aA = sb + (u32)((w*16 + (g&1)*8 + lr)*STB + (g>>1)*16);
    const u32 aB = sb + 2*TILE_B + (u32)(((g>>1)*8 + lr)*STB + (g&1)*16);

    float acc[16][4];
    #pragma unroll
    for (int nb = 0; nb < 16; nb++)
        #pragma unroll
        for (int e = 0; e < 4; e++) acc[nb][e] = 0.f;

    for (int ch = 0; ch < 2; ch++) {
        __syncthreads();
        #pragma unroll
        for (int i = 0; i < 32; i++) {
            int f = tid + i*256;
            int t4 = f >> 11, idx = f & 2047;
            int row = idx >> 4, c16 = idx & 15;
            const u32* src;
            if (t4 < 2)
                src = (t4 ? d_xl : d_xh) + (size_t)(b*NN + n0 + row)*128 + ch*64 + c16*4;
            else
                src = ((t4==2) ? d_Wh : d_Wl) + (size_t)(z*CSd + row)*128 + ch*64 + c16*4;
            *(uint4*)(smem + t4*TILE_B + row*STB + c16*16) = *(const uint4*)src;
        }
        __syncthreads();
        #pragma unroll
        for (int ks = 0; ks < 8; ks++) {
            u32 ah[4], al[4];
            ldsm_x4(ah[0],ah[1],ah[2],ah[3], aA + ks*32);
            ldsm_x4(al[0],al[1],al[2],al[3], aA + TILE_B + ks*32);
            #pragma unroll
            for (int nbp = 0; nbp < 8; nbp++) {
                u32 bh[4], blo[4];
                ldsm_x4(bh[0],bh[1],bh[2],bh[3],     aB + nbp*16*STB + ks*32);
                ldsm_x4(blo[0],blo[1],blo[2],blo[3], aB + TILE_B + nbp*16*STB + ks*32);
                mma_bf16(acc[2*nbp],   ah, &bh[0]);
                mma_bf16(acc[2*nbp],   ah, &blo[0]);
                mma_bf16(acc[2*nbp],   al, &bh[0]);
                mma_bf16(acc[2*nbp+1], ah, &bh[2]);
                mma_bf16(acc[2*nbp+1], ah, &blo[2]);
                mma_bf16(acc[2*nbp+1], al, &bh[2]);
            }
        }
    }

    u32* oh = (z==0) ? d_Qh : (z==1) ? d_Kh : d_Vh;
    u32* ol = (z==0) ? d_Ql : (z==1) ? d_Kl : d_Vl;
    int r0 = n0 + w*16 + (lane >> 2);
    #pragma unroll
    for (int nb = 0; nb < 16; nb++) {
        int col = nb*8 + quad*2;
        float b0 = __ldg(&bias[col]), b1 = __ldg(&bias[col+1]);
        #pragma unroll
        for (int half = 0; half < 2; half++) {
            float v0 = (acc[nb][2*half]   + b0) * qsc;
            float v1 = (acc[nb][2*half+1] + b1) * qsc;
            u32 h = cvt_bf2(v1, v0);
            float f1 = __uint_as_float(h & 0xffff0000u);
            float f0 = __uint_as_float(h << 16);
            size_t u = (size_t)(b*NN + r0 + half*8)*64 + nb*4 + quad;
            oh[u] = h;
            ol[u] = cvt_bf2(v1 - f1, v0 - f0);
        }
    }
}

// ======================= Kernel B: HMMA flash attention (cp.async) ==========
#define OFF_QH 0
#define OFF_QL (1*TILE_B)
#define OFF_KH (2*TILE_B)
#define OFF_KL (3*TILE_B)
#define OFF_VH (4*TILE_B)
#define OFF_VL (5*TILE_B)
#define ATTN_SMEM_BYTES (6*TILE_B)

__device__ __forceinline__ void issue_kv(u32 sb, int tid, int b, int kb,
                                         int voff, const u32* ph, const u32* pl)
{
    #pragma unroll
    for (int i = 0; i < 16; i++) {
        int f = tid + i*256;
        int sp = f >> 11, idx = f & 2047;
        int row = idx >> 4, c16 = idx & 15;
        const u32* src = (sp ? pl : ph) + (size_t)(b*NN + kb + row)*64 + c16*4;
        CP16(sb + (u32)(voff + sp*TILE_B + row*STB + c16*16), src);
    }
}

__global__ __launch_bounds__(256, 1) void attn_kernel()
{
    extern __shared__ __align__(16) char smem[];
    const u32 sb = smem_u32(smem);
    const int b  = blockIdx.y;
    const int q0 = blockIdx.x * 128;
    const int tid = threadIdx.x;
    const int w = tid >> 5, lane = tid & 31;
    const int g = lane >> 3, lr = lane & 7, quad = lane & 3;

    #pragma unroll
    for (int i = 0; i < 16; i++) {
        int f = tid + i*256;
        int sp = f >> 11, idx = f & 2047;
        int row = idx >> 4, c16 = idx & 15;
        const u32* src = (sp ? d_Ql : d_Qh) + (size_t)(b*NN + q0 + row)*64 + c16*4;
        *(uint4*)(smem + (sp ? OFF_QL : OFF_QH) + row*STB + c16*16) = *(const uint4*)src;
    }

    const u32 aQh = sb + OFF_QH + (u32)((w*16 + (g&1)*8 + lr)*STB + (g>>1)*16);
    const u32 aQl = aQh + TILE_B;
    const u32 aKoff = (u32)(((g>>1)*8 + lr)*STB + (g&1)*16);
    const u32 aKh = sb + OFF_KH + aKoff;
    const u32 aKl = sb + OFF_KL + aKoff;
    const u32 aVoff = (u32)(((g&1)*8 + lr)*STB + (g>>1)*16);
    const u32 aVh = sb + OFF_VH + aVoff;
    const u32 aVl = sb + OFF_VL + aVoff;

    float o[16][4];
    #pragma unroll
    for (int nb = 0; nb < 16; nb++)
        #pragma unroll
        for (int e = 0; e < 4; e++) o[nb][e] = 0.f;
    float m0 = -1e30f, m1 = -1e30f, l0 = 0.f, l1 = 0.f;

    issue_kv(sb, tid, b, 0, OFF_KH, d_Kh, d_Kl); CP_COMMIT();
    issue_kv(sb, tid, b, 0, OFF_VH, d_Vh, d_Vl); CP_COMMIT();

    for (int kt = 0; kt < NN/128; kt++) {
        CP_WAIT1();
        __syncthreads();

        float s[16][4];
        #pragma unroll
        for (int nb = 0; nb < 16; nb++)
            #pragma unroll
            for (int e = 0; e < 4; e++) s[nb][e] = 0.f;
        #pragma unroll
        for (int ks = 0; ks < 8; ks++) {
            u32 ah[4], al[4];
            ldsm_x4(ah[0],ah[1],ah[2],ah[3], aQh + ks*32);
            ldsm_x4(al[0],al[1],al[2],al[3], aQl + ks*32);
            #pragma unroll
            for (int nbp = 0; nbp < 8; nbp++) {
                u32 kh[4], kl[4];
                ldsm_x4(kh[0],kh[1],kh[2],kh[3], aKh + nbp*16*STB + ks*32);
                ldsm_x4(kl[0],kl[1],kl[2],kl[3], aKl + nbp*16*STB + ks*32);
                mma_bf16(s[2*nbp],   ah, &kh[0]);
                mma_bf16(s[2*nbp],   ah, &kl[0]);
                mma_bf16(s[2*nbp],   al, &kh[0]);
                mma_bf16(s[2*nbp+1], ah, &kh[2]);
                mma_bf16(s[2*nbp+1], ah, &kl[2]);
                mma_bf16(s[2*nbp+1], al, &kh[2]);
            }
        }
        __syncthreads();
        if (kt + 1 < NN/128)
            issue_kv(sb, tid, b, (kt+1)*128, OFF_KH, d_Kh, d_Kl);
        CP_COMMIT();

        // ---- online softmax in log2 domain (q pre-scaled by log2e) ----
        float tm0 = -1e30f, tm1 = -1e30f;
        #pragma unroll
        for (int nb = 0; nb < 16; nb++) {
            tm0 = fmaxf(tm0, fmaxf(s[nb][0], s[nb][1]));
            tm1 = fmaxf(tm1, fmaxf(s[nb][2], s[nb][3]));
        }
        tm0 = fmaxf(tm0, __shfl_xor_sync(0xffffffffu, tm0, 1));
        tm0 = fmaxf(tm0, __shfl_xor_sync(0xffffffffu, tm0, 2));
        tm1 = fmaxf(tm1, __shfl_xor_sync(0xffffffffu, tm1, 1));
        tm1 = fmaxf(tm1, __shfl_xor_sync(0xffffffffu, tm1, 2));
        float nm0 = fmaxf(m0, tm0), nm1 = fmaxf(m1, tm1);
        float rs0 = ex2f(m0 - nm0), rs1 = ex2f(m1 - nm1);
        m0 = nm0; m1 = nm1;
        float ps0 = 0.f, ps1 = 0.f;
        #pragma unroll
        for (int nb = 0; nb < 16; nb++) {
            s[nb][0] = ex2f(s[nb][0] - nm0);
            s[nb][1] = ex2f(s[nb][1] - nm0);
            s[nb][2] = ex2f(s[nb][2] - nm1);
            s[nb][3] = ex2f(s[nb][3] - nm1);
            ps0 += s[nb][0] + s[nb][1];
            ps1 += s[nb][2] + s[nb][3];
            o[nb][0] *= rs0; o[nb][1] *= rs0;
            o[nb][2] *= rs1; o[nb][3] *= rs1;
        }
        ps0 += __shfl_xor_sync(0xffffffffu, ps0, 1);
        ps0 += __shfl_xor_sync(0xffffffffu, ps0, 2);
        ps1 += __shfl_xor_sync(0xffffffffu, ps1, 1);
        ps1 += __shfl_xor_sync(0xffffffffu, ps1, 2);
        l0 = l0*rs0 + ps0;
        l1 = l1*rs1 + ps1;

        CP_WAIT1();
        __syncthreads();

        #pragma unroll
        for (int ks2 = 0; ks2 < 8; ks2++) {
            u32 pah[4], pal[4];
            pah[0] = cvt_bf2(s[2*ks2][1],   s[2*ks2][0]);
            pah[1] = cvt_bf2(s[2*ks2][3],   s[2*ks2][2]);
            pah[2] = cvt_bf2(s[2*ks2+1][1], s[2*ks2+1][0]);
            pah[3] = cvt_bf2(s[2*ks2+1][3], s[2*ks2+1][2]);
            #pragma unroll
            for (int u2 = 0; u2 < 4; u2++) {
                int nb = 2*ks2 + (u2 >> 1);
                int e  = (u2 & 1) * 2;
                float f0 = __uint_as_float(pah[u2] << 16);
                float f1 = __uint_as_float(pah[u2] & 0xffff0000u);
                pal[u2] = cvt_bf2(s[nb][e+1] - f1, s[nb][e] - f0);
            }
            #pragma unroll
            for (int nbp = 0; nbp < 8; nbp++) {
                u32 vh[4], vl[4];
                ldsm_x4_t(vh[0],vh[1],vh[2],vh[3], aVh + ks2*16*STB + nbp*32);
                ldsm_x4_t(vl[0],vl[1],vl[2],vl[3], aVl + ks2*16*STB + nbp*32);
                mma_bf16(o[2*nbp],   pah, &vh[0]);
                mma_bf16(o[2*nbp],   pah, &vl[0]);
                mma_bf16(o[2*nbp],   pal, &vh[0]);
                mma_bf16(o[2*nbp+1], pah, &vh[2]);
                mma_bf16(o[2*nbp+1], pah, &vl[2]);
                mma_bf16(o[2*nbp+1], pal, &vh[2]);
            }
        }
        __syncthreads();
        if (kt + 1 < NN/128)
            issue_kv(sb, tid, b, (kt+1)*128, OFF_VH, d_Vh, d_Vl);
        CP_COMMIT();
    }

    // ---- epilogue: normalize, split to bf16 hi/lo, write d_Oh/d_Ol ----
    float inv0 = 1.0f / l0, inv1 = 1.0f / l1;
    int r0g = q0 + w*16 + (lane >> 2);
    #pragma unroll
    for (int nb = 0; nb < 16; nb++) {
        #pragma unroll
        for (int half = 0; half < 2; half++) {
            float v0 = o[nb][2*half]   * (half ? inv1 : inv0);
            float v1 = o[nb][2*half+1] * (half ? inv1 : inv0);
            u32 h = cvt_bf2(v1, v0);
            float f1 = __uint_as_float(h & 0xffff0000u);
            float f0 = __uint_as_float(h << 16);
            size_t u = (size_t)(b*NN + r0g + half*8)*64 + nb*4 + quad;
            d_Oh[u] = h;
            d_Ol[u] = cvt_bf2(v1 - f1, v0 - f0);
        }
    }
}

// ======================= Kernel C: output projection (HMMA) =================
// grid (32 ntile, 2 ctile, B). y[n][c] fragments -> smem transpose -> d_Y[c][n]
#define OPROJ_SMEM (4*TILE_B + 128*132*4)

__global__ __launch_bounds__(256, 1) void oproj_kernel(const float* __restrict__ bo)
{
    extern __shared__ __align__(16) char smem[];
    const u32 sb = smem_u32(smem);
    const int b  = blockIdx.z;
    const int c0 = blockIdx.y * 128;
    const int n0 = blockIdx.x * 128;
    const int tid = threadIdx.x;
    const int w = tid >> 5, lane = tid & 31;
    const int g = lane >> 3, lr = lane & 7, quad = lane & 3;

    #pragma unroll
    for (int i = 0; i < 32; i++) {
        int f = tid + i*256;
        int t4 = f >> 11, idx = f & 2047;
        int row = idx >> 4, c16 = idx & 15;
        const u32* src;
        if (t4 < 2)
            src = (t4 ? d_Ol : d_Oh) + (size_t)(b*NN + n0 + row)*64 + c16*4;
        else
            src = ((t4==2) ? d_Woh : d_Wol) + (size_t)(c0 + row)*64 + c16*4;
        *(uint4*)(smem + t4*TILE_B + row*STB + c16*16) = *(const uint4*)src;
    }
    __syncthreads();

    const u32 aA = sb + (u32)((w*16 + (g&1)*8 + lr)*STB + (g>>1)*16);
    const u32 aB = sb + 2*TILE_B + (u32)(((g>>1)*8 + lr)*STB + (g&1)*16);

    float acc[16][4];
    #pragma unroll
    for (int nb = 0; nb < 16; nb++)
        #pragma unroll
        for (int e = 0; e < 4; e++) acc[nb][e] = 0.f;

    #pragma unroll
    for (int ks = 0; ks < 8; ks++) {
        u32 ah[4], al[4];
        ldsm_x4(ah[0],ah[1],ah[2],ah[3], aA + ks*32);
        ldsm_x4(al[0],al[1],al[2],al[3], aA + TILE_B + ks*32);
        #pragma unroll
        for (int nbp = 0; nbp < 8; nbp++) {
            u32 bh[4], blo[4];
            ldsm_x4(bh[0],bh[1],bh[2],bh[3],     aB + nbp*16*STB + ks*32);
            ldsm_x4(blo[0],blo[1],blo[2],blo[3], aB + TILE_B + nbp*16*STB + ks*32);
            mma_bf16(acc[2*nbp],   ah, &bh[0]);
            mma_bf16(acc[2*nbp],   ah, &blo[0]);
            mma_bf16(acc[2*nbp],   al, &bh[0]);
            mma_bf16(acc[2*nbp+1], ah, &bh[2]);
            mma_bf16(acc[2*nbp+1], ah, &blo[2]);
            mma_bf16(acc[2*nbp+1], al, &bh[2]);
        }
    }
    __syncthreads();

    // ---- transpose fragments into ys[c][n] (stride 132, conflict-free) ----
    float* ys = (float*)(smem + 4*TILE_B);
    int r0 = w*16 + (lane >> 2);
    #pragma unroll
    for (int nb = 0; nb < 16; nb++) {
        int col = nb*8 + quad*2;
        float b0 = __ldg(&bo[c0+col]), b1 = __ldg(&bo[c0+col+1]);
        ys[col*132 + r0]         = acc[nb][0] + b0;
        ys[(col+1)*132 + r0]     = acc[nb][1] + b1;
        ys[col*132 + r0 + 8]     = acc[nb][2] + b0;
        ys[(col+1)*132 + r0 + 8] = acc[nb][3] + b1;
    }
    __syncthreads();

    // ---- per-channel partial sums (for BN stats) ----
    {
        int c = tid >> 1, hn = (tid & 1) * 64;
        float s = 0.f, s2 = 0.f;
        #pragma unroll 8
        for (int j = 0; j < 64; j++) {
            float v = ys[c*132 + hn + j];
            s += v; s2 += v*v;
        }
        s  += __shfl_xor_sync(0xffffffffu, s, 1);
        s2 += __shfl_xor_sync(0xffffffffu, s2, 1);
        if (!(tid & 1)) {
            int j = b*32 + blockIdx.x;
            d_ps1[(size_t)j*CC + c0 + c] = s;
            d_ps2[(size_t)j*CC + c0 + c] = s2;
        }
    }

    // ---- coalesced global write d_Y[b][c][n] ----
    #pragma unroll
    for (int i = 0; i < 16; i++) {
        int f = tid + i*256;
        int row = f >> 5, q4 = f & 31;
        *(float4*)&d_Y[(size_t)(b*CC + c0 + row)*NN + n0 + q4*4] =
            *(float4*)&ys[row*132 + q4*4];
    }
}

// ======================= Kernel D: BN stats from partials ===================
__global__ __launch_bounds__(256) void bnstat_kernel(
    const float* __restrict__ gamma, const float* __restrict__ beta)
{
    const int c = threadIdx.x;
    float s = 0.f, s2 = 0.f;
    #pragma unroll 8
    for (int j = 0; j < 128; j++) {
        s  += d_ps1[(size_t)j*CC + c];
        s2 += d_ps2[(size_t)j*CC + c];
    }
    float mean = s  * (1.f/16384.f);
    float var  = s2 * (1.f/16384.f) - mean*mean;
    float sc = gamma[c] * rsqrtf(var + EPSc);
    d_scale[c] = sc;
    d_shift[c] = beta[c] - mean*sc;
}

// ======================= Kernel E: BN affine + ReLU + residual ==============
__global__ __launch_bounds__(256) void epilogue_kernel(
    const float* __restrict__ x, float* __restrict__ out)
{
    int i4 = blockIdx.x*256 + threadIdx.x;
    int idx = i4 * 4;
    int c = (idx >> 12) & 255;
    float sc = d_scale[c], sh = d_shift[c];
    float4 y   = *(const float4*)&d_Y[idx];
    float4 xin = ((const float4*)x)[i4];
    float4 r;
    r.x = fmaxf(fmaf(y.x, sc, sh), 0.f) + xin.x;
    r.y = fmaxf(fmaf(y.y, sc, sh), 0.f) + xin.y;
    r.z = fmaxf(fmaf(y.z, sc, sh), 0.f) + xin.z;
    r.w = fmaxf(fmaf(y.w, sc, sh), 0.f) + xin.w;
    ((float4*)out)[i4] = r;
}

// ============================ launch =======================================
extern "C" void kernel_launch(void* const* d_in, const int* in_sizes, int n_in,
                              void* d_out, int out_size)
{
    const float* x     = (const float*)d_in[0];
    const float* Wq    = (const float*)d_in[1];
    const float* bq    = (const float*)d_in[2];
    const float* Wk    = (const float*)d_in[3];
    const float* bk    = (const float*)d_in[4];
    const float* Wv    = (const float*)d_in[5];
    const float* bv    = (const float*)d_in[6];
    const float* Wo    = (const float*)d_in[7];
    const float* bo    = (const float*)d_in[8];
    const float* gamma = (const float*)d_in[9];
    const float* beta  = (const float*)d_in[10];
    float* out = (float*)d_out;

    cudaFuncSetAttribute(attn_kernel,
                         cudaFuncAttributeMaxDynamicSharedMemorySize, ATTN_SMEM_BYTES);
    cudaFuncSetAttribute(qkv_kernel,
                         cudaFuncAttributeMaxDynamicSharedMemorySize, QKV_SMEM);
    cudaFuncSetAttribute(oproj_kernel,
                         cudaFuncAttributeMaxDynamicSharedMemorySize, OPROJ_SMEM);

    wsplit_kernel<<<dim3(8, 4), 256>>>(Wq, Wk, Wv, Wo);
    xsplit_kernel<<<dim3(NN/64, CC/64, BB), 256>>>(x);
    qkv_kernel<<<dim3(NN/128, BB, 3), 256, QKV_SMEM>>>(bq, bk, bv);
    attn_kernel<<<dim3(NN/128, BB), 256, ATTN_SMEM_BYTES>>>();
    oproj_kernel<<<dim3(NN/128, CC/128, BB), 256, OPROJ_SMEM>>>(bo);
    bnstat_kernel<<<1, 256>>>(gamma, beta);
    epilogue_kernel<<<(BB*CC*NN)/4/256, 256>>>(x, out);
}